// round 6
// baseline (speedup 1.0000x reference)
#include <cuda_runtime.h>

#define NCLS   8192
#define NBATCH 8192
#define THREADS 256
#define EPSF 1e-8f
#define DEPTH_PARAM 0.1f
#define DMAX 32

// Global accumulator + completion counter. Zero-initialized at module load;
// the last-finishing block resets both before the kernel ends, so every
// kernel_launch call starts from identical state.
__device__ double       g_acc;
__device__ unsigned int g_done;

// min 6 CTAs/SM -> ptxas caps at ~42 regs: keeps 48 warps/SM resident while
// allowing 4 independent LDG.128 in flight per warp (R4 failed at 62 regs /
// 4 CTAs; R5 baseline is 32 regs / MLP~2).
__global__ __launch_bounds__(THREADS, 6)
void chce_fused_kernel(const float* __restrict__ y_pred,
                       const float* __restrict__ y_true,
                       const float* __restrict__ class_w,
                       const int*   __restrict__ tree_paths,
                       const int*   __restrict__ tree_lens,
                       float*       __restrict__ out,
                       int D)
{
    const int b   = blockIdx.x;
    const int tid = threadIdx.x;

    const float4* yp = reinterpret_cast<const float4*>(y_pred) + (size_t)b * (NCLS / 4);
    const float4* yt = reinterpret_cast<const float4*>(y_true) + (size_t)b * (NCLS / 4);

    float sumexp = 0.0f;
    float best_v = -3.402823466e38f;
    int   best_i = 0;

    // Fused streaming pass; 4 independent float4 LDGs front-loaded per
    // iteration, evict-first on both streams.
    #pragma unroll
    for (int it = 0; it < (NCLS / 4) / THREADS / 2; ++it) {
        const int i0 = tid + (2 * it)     * THREADS;
        const int i1 = tid + (2 * it + 1) * THREADS;
        float4 p0 = __ldcs(&yp[i0]);
        float4 p1 = __ldcs(&yp[i1]);
        float4 t0 = __ldcs(&yt[i0]);
        float4 t1 = __ldcs(&yt[i1]);

        sumexp += __expf(p0.x) + __expf(p0.y) + __expf(p0.z) + __expf(p0.w);
        sumexp += __expf(p1.x) + __expf(p1.y) + __expf(p1.z) + __expf(p1.w);

        const int b0 = i0 * 4;
        if (t0.x > best_v) { best_v = t0.x; best_i = b0 + 0; }
        if (t0.y > best_v) { best_v = t0.y; best_i = b0 + 1; }
        if (t0.z > best_v) { best_v = t0.z; best_i = b0 + 2; }
        if (t0.w > best_v) { best_v = t0.w; best_i = b0 + 3; }
        const int b1 = i1 * 4;
        if (t1.x > best_v) { best_v = t1.x; best_i = b1 + 0; }
        if (t1.y > best_v) { best_v = t1.y; best_i = b1 + 1; }
        if (t1.z > best_v) { best_v = t1.z; best_i = b1 + 2; }
        if (t1.w > best_v) { best_v = t1.w; best_i = b1 + 3; }
    }

    // Warp reduction: sum for sumexp, (max value, min index on tie) for argmax.
    const unsigned mask = 0xffffffffu;
    #pragma unroll
    for (int off = 16; off > 0; off >>= 1) {
        float ov = __shfl_down_sync(mask, best_v, off);
        int   oi = __shfl_down_sync(mask, best_i, off);
        float os = __shfl_down_sync(mask, sumexp, off);
        sumexp += os;
        if (ov > best_v || (ov == best_v && oi < best_i)) { best_v = ov; best_i = oi; }
    }

    __shared__ float sh_v[THREADS / 32];
    __shared__ int   sh_i[THREADS / 32];
    __shared__ float sh_s[THREADS / 32];
    const int warp = tid >> 5;
    const int lane = tid & 31;
    if (lane == 0) { sh_v[warp] = best_v; sh_i[warp] = best_i; sh_s[warp] = sumexp; }
    __syncthreads();

    if (tid == 0) {
        float S  = sh_s[0];
        float bv = sh_v[0];
        int   bi = sh_i[0];
        #pragma unroll
        for (int w = 1; w < THREADS / 32; ++w) {
            S += sh_s[w];
            if (sh_v[w] > bv || (sh_v[w] == bv && sh_i[w] < bi)) { bv = sh_v[w]; bi = sh_i[w]; }
        }

        const int label = bi;
        const int len   = tree_lens[label];
        const float invS = 1.0f / S;
        const int* path = tree_paths + (size_t)label * D;

        // Gather path probabilities (padded levels -> 0, matching node_mask).
        float pr[DMAX];
        for (int k = 0; k < D; ++k) {
            float v = 0.0f;
            if (k < len) {
                const int node = path[k];
                v = expf(y_pred[(size_t)b * NCLS + node]) * invS;
            }
            pr[k] = v;
        }

        // Suffix sums s[k] = sum_{j>=k} pr[j]; s[D] = 0 (reference's s_next pad).
        float s_arr[DMAX + 1];
        s_arr[D] = 0.0f;
        for (int k = D - 1; k >= 0; --k) s_arr[k] = s_arr[k + 1] + pr[k];

        float path_loss = 0.0f;
        for (int k = 0; k < len - 1; ++k) {        // valid = k < len-1
            const float cond = s_arr[k] / (s_arr[k + 1] + EPSF);
            const float h    = (float)(len - 1 - k);
            const float w    = expf(-DEPTH_PARAM * h);
            path_loss += w * logf(cond + EPSF);
        }

        atomicAdd(&g_acc, (double)(-class_w[label] * path_loss));

        // Last-block-done finalize: make our add visible, then count in.
        __threadfence();
        const unsigned ticket = atomicAdd(&g_done, 1u);
        if (ticket == NBATCH - 1) {
            const unsigned long long raw =
                atomicExch(reinterpret_cast<unsigned long long*>(&g_acc), 0ull);
            const double acc = __longlong_as_double((long long)raw);
            out[0] = (float)(acc / (double)NBATCH);
            g_done = 0;   // reset counter for the next launch (stream-ordered)
        }
    }
}

extern "C" void kernel_launch(void* const* d_in, const int* in_sizes, int n_in,
                              void* d_out, int out_size)
{
    const float* y_pred     = (const float*)d_in[0];
    const float* y_true     = (const float*)d_in[1];
    const float* class_w    = (const float*)d_in[2];
    const int*   tree_paths = (const int*)  d_in[3];
    const int*   tree_lens  = (const int*)  d_in[4];

    const int D = in_sizes[3] / NCLS;

    chce_fused_kernel<<<NBATCH, THREADS>>>(y_pred, y_true, class_w,
                                           tree_paths, tree_lens,
                                           (float*)d_out, D);
}

// round 7
// speedup vs baseline: 1.0804x; 1.0804x over previous
#include <cuda_runtime.h>

#define NCLS   8192
#define NBATCH 8192
#define THREADS 256
#define NWARPS (THREADS / 32)
#define EPSF 1e-8f
#define DEPTH_PARAM 0.1f
#define FULLMASK 0xffffffffu

// Global accumulator + completion counter. Zero-initialized at module load;
// the last-finishing block resets both before the kernel ends, so every
// kernel_launch call starts from identical state.
__device__ double       g_acc;
__device__ unsigned int g_done;

__global__ __launch_bounds__(THREADS)
void chce_fused_kernel(const float* __restrict__ y_pred,
                       const float* __restrict__ y_true,
                       const float* __restrict__ class_w,
                       const int*   __restrict__ tree_paths,
                       const int*   __restrict__ tree_lens,
                       float*       __restrict__ out,
                       int D)
{
    const int b   = blockIdx.x;
    const int tid = threadIdx.x;
    const int lane = tid & 31;
    const int warp = tid >> 5;

    const float4* yp = reinterpret_cast<const float4*>(y_pred) + (size_t)b * (NCLS / 4);
    const float4* yt = reinterpret_cast<const float4*>(y_true) + (size_t)b * (NCLS / 4);

    float sumexp = 0.0f;
    float best_v = -3.402823466e38f;
    int   best_i = 0;

    // Single fused streaming pass over both rows; evict-first on both streams
    // (R5 shape: 32 regs, max occupancy — batching regressed twice).
    #pragma unroll
    for (int it = 0; it < (NCLS / 4) / THREADS; ++it) {
        const int idx = tid + it * THREADS;
        float4 t = __ldcs(&yt[idx]);
        float4 p = __ldcs(&yp[idx]);

        sumexp += __expf(p.x) + __expf(p.y) + __expf(p.z) + __expf(p.w);

        const int base = idx * 4;
        if (t.x > best_v) { best_v = t.x; best_i = base + 0; }
        if (t.y > best_v) { best_v = t.y; best_i = base + 1; }
        if (t.z > best_v) { best_v = t.z; best_i = base + 2; }
        if (t.w > best_v) { best_v = t.w; best_i = base + 3; }
    }

    // Warp reduction: sum for sumexp, (max value, min index on tie) for argmax.
    #pragma unroll
    for (int off = 16; off > 0; off >>= 1) {
        float ov = __shfl_down_sync(FULLMASK, best_v, off);
        int   oi = __shfl_down_sync(FULLMASK, best_i, off);
        float os = __shfl_down_sync(FULLMASK, sumexp, off);
        sumexp += os;
        if (ov > best_v || (ov == best_v && oi < best_i)) { best_v = ov; best_i = oi; }
    }

    __shared__ float sh_v[NWARPS];
    __shared__ int   sh_i[NWARPS];
    __shared__ float sh_s[NWARPS];
    if (lane == 0) { sh_v[warp] = best_v; sh_i[warp] = best_i; sh_s[warp] = sumexp; }
    __syncthreads();

    // ---- Parallel epilogue: warp 0 only ----
    if (warp == 0) {
        // Cross-warp combine in registers (NWARPS=8 lanes participate).
        float v = (lane < NWARPS) ? sh_v[lane] : -3.402823466e38f;
        int   i = (lane < NWARPS) ? sh_i[lane] : 0x7fffffff;
        float s = (lane < NWARPS) ? sh_s[lane] : 0.0f;
        #pragma unroll
        for (int off = 4; off > 0; off >>= 1) {
            float ov = __shfl_down_sync(FULLMASK, v, off);
            int   oi = __shfl_down_sync(FULLMASK, i, off);
            float os = __shfl_down_sync(FULLMASK, s, off);
            s += os;
            if (ov > v || (ov == v && oi < i)) { v = ov; i = oi; }
        }
        const float S     = __shfl_sync(FULLMASK, s, 0);
        const int   label = __shfl_sync(FULLMASK, i, 0);
        const float invS  = 1.0f / S;

        const int len = tree_lens[label];   // same addr all lanes: broadcast

        // Parallel path gather: lane k handles level k (pr=0 beyond len,
        // matching the reference node_mask).
        float pr = 0.0f;
        if (lane < len && lane < D) {
            const int node = tree_paths[(size_t)label * D + lane];
            pr = expf(y_pred[(size_t)b * NCLS + node]) * invS;
        }

        // Reverse inclusive suffix scan: sarr[k] = sum_{j>=k} pr[j].
        float sarr = pr;
        #pragma unroll
        for (int off = 1; off < 32; off <<= 1) {
            float t = __shfl_down_sync(FULLMASK, sarr, off);
            if (lane + off < 32) sarr += t;
        }
        float snext = __shfl_down_sync(FULLMASK, sarr, 1);
        if (lane == 31) snext = 0.0f;

        // Per-level loss terms in parallel (valid: k < len-1).
        float term = 0.0f;
        if (lane < len - 1) {
            const float cond = sarr / (snext + EPSF);
            const float h    = (float)(len - 1 - lane);
            term = expf(-DEPTH_PARAM * h) * logf(cond + EPSF);
        }
        #pragma unroll
        for (int off = 16; off > 0; off >>= 1)
            term += __shfl_down_sync(FULLMASK, term, off);

        if (lane == 0) {
            atomicAdd(&g_acc, (double)(-class_w[label] * term));

            // Last-block-done finalize: make our add visible, then count in.
            __threadfence();
            const unsigned ticket = atomicAdd(&g_done, 1u);
            if (ticket == NBATCH - 1) {
                const unsigned long long raw =
                    atomicExch(reinterpret_cast<unsigned long long*>(&g_acc), 0ull);
                const double acc = __longlong_as_double((long long)raw);
                out[0] = (float)(acc / (double)NBATCH);
                g_done = 0;   // reset for the next launch (stream-ordered)
            }
        }
    }
}

extern "C" void kernel_launch(void* const* d_in, const int* in_sizes, int n_in,
                              void* d_out, int out_size)
{
    const float* y_pred     = (const float*)d_in[0];
    const float* y_true     = (const float*)d_in[1];
    const float* class_w    = (const float*)d_in[2];
    const int*   tree_paths = (const int*)  d_in[3];
    const int*   tree_lens  = (const int*)  d_in[4];

    const int D = in_sizes[3] / NCLS;

    chce_fused_kernel<<<NBATCH, THREADS>>>(y_pred, y_true, class_w,
                                           tree_paths, tree_lens,
                                           (float*)d_out, D);
}